// round 2
// baseline (speedup 1.0000x reference)
#include <cuda_runtime.h>

#define DIM 128
#define SA 132   // smem stride (floats) for activation tile (k-major)
#define SW 132   // smem stride (floats) for weight tiles (k-major)
#define THREADS 512
#define PI_F 3.14159265358979323846f

// ---------- packed f32x2 helpers (sm_103a FFMA2 path) ----------
__device__ __forceinline__ unsigned long long pack_dup(float a) {
    unsigned long long r;
    asm("mov.b64 %0, {%1, %1};" : "=l"(r) : "f"(a));
    return r;
}
__device__ __forceinline__ void ffma2(unsigned long long& acc,
                                      unsigned long long a,
                                      unsigned long long b) {
    asm("fma.rn.f32x2 %0, %1, %2, %0;" : "+l"(acc) : "l"(a), "l"(b));
}
__device__ __forceinline__ float2 unpack2(unsigned long long v) {
    float2 f;
    asm("mov.b64 {%0, %1}, %2;" : "=f"(f.x), "=f"(f.y) : "l"(v));
    return f;
}
__device__ __forceinline__ float silu_f(float z) {
    return z / (1.0f + __expf(-z));
}

// K=128 loop; each thread: 4 rows (ty*4..+3) x 8 cols (tx*4..+3, 64+tx*4..+3)
__device__ __forceinline__ void gemm128(const float* __restrict__ sAct,
                                        const float* __restrict__ sWt,
                                        int tx, int ty,
                                        unsigned long long acc[4][4]) {
#pragma unroll
    for (int i = 0; i < 4; ++i)
#pragma unroll
        for (int p = 0; p < 4; ++p) acc[i][p] = 0ULL;

#pragma unroll 4
    for (int k = 0; k < DIM; ++k) {
        const float4 a = *(const float4*)(sAct + k * SA + ty * 4);
        const ulonglong2 w0 = *(const ulonglong2*)(sWt + k * SW + tx * 4);
        const ulonglong2 w1 = *(const ulonglong2*)(sWt + k * SW + 64 + tx * 4);

        unsigned long long aa[4];
        aa[0] = pack_dup(a.x); aa[1] = pack_dup(a.y);
        aa[2] = pack_dup(a.z); aa[3] = pack_dup(a.w);

#pragma unroll
        for (int i = 0; i < 4; ++i) {
            ffma2(acc[i][0], aa[i], w0.x);
            ffma2(acc[i][1], aa[i], w0.y);
            ffma2(acc[i][2], aa[i], w1.x);
            ffma2(acc[i][3], aa[i], w1.y);
        }
    }
}

__global__ void __launch_bounds__(THREADS, 1)
fused_timestep_mlp(const float* __restrict__ t,
                   const float* __restrict__ W1,
                   const float* __restrict__ b1,
                   const float* __restrict__ W2,
                   const float* __restrict__ b2,
                   float* __restrict__ out) {
    extern __shared__ float sm[];
    float* sW1 = sm;                  // [128][SW] k-major: sW1[k*SW+o] = W1[o][k]
    float* sW2 = sm + DIM * SW;
    float* sA  = sm + 2 * DIM * SW;   // [128][SA] k-major activations

    const int tid = threadIdx.x;
    const int tx = tid & 15;          // 16 col groups
    const int ty = tid >> 4;          // 32 row groups (4 rows each)
    const int rowBase = blockIdx.x * DIM;

    // ---- Phase 1: load W1/W2 transposed into smem ----
    {
        const int o   = tid & 127;    // output index (smem col)
        const int kq0 = tid >> 7;     // 0..3
#pragma unroll
        for (int it = 0; it < 8; ++it) {
            const int kq = kq0 + it * 4;  // 0..31 k-quads
            const float4 v1 = *(const float4*)(W1 + o * DIM + kq * 4);
            const float4 v2 = *(const float4*)(W2 + o * DIM + kq * 4);
            sW1[(kq * 4 + 0) * SW + o] = v1.x;
            sW1[(kq * 4 + 1) * SW + o] = v1.y;
            sW1[(kq * 4 + 2) * SW + o] = v1.z;
            sW1[(kq * 4 + 3) * SW + o] = v1.w;
            sW2[(kq * 4 + 0) * SW + o] = v2.x;
            sW2[(kq * 4 + 1) * SW + o] = v2.y;
            sW2[(kq * 4 + 2) * SW + o] = v2.z;
            sW2[(kq * 4 + 3) * SW + o] = v2.w;
        }
    }

    // ---- Phase 2: timestep embedding, stored k-major sA[d][row] ----
    {
        const int row = tid >> 2;         // 0..127
        const int d0  = (tid & 3) * 32;   // 4 threads per row, 32 dims each
        const float tv = t[rowBase + row];
        const float p1 = tv * (PI_F / 128.0f);
        const float p2 = (1.0f - tv) * (PI_F / 128.0f);
#pragma unroll 8
        for (int j = 0; j < 32; ++j) {
            const int d = d0 + j;
            const float df = (float)d;
            sA[d * SA + row] = tv * __cosf(df * p1) + tv * __sinf(df * p2);
        }
    }
    __syncthreads();

    unsigned long long acc[4][4];
    float rb[8];

    // ---- Layer 1 ----
    gemm128(sA, sW1, tx, ty, acc);
#pragma unroll
    for (int j = 0; j < 4; ++j) {
        rb[j]     = b1[tx * 4 + j];
        rb[4 + j] = b1[64 + tx * 4 + j];
    }
    float h[4][8];
#pragma unroll
    for (int i = 0; i < 4; ++i) {
#pragma unroll
        for (int p = 0; p < 4; ++p) {
            const float2 z = unpack2(acc[i][p]);
            const int j = 2 * p;
            h[i][j]     = silu_f(z.x + rb[j]);
            h[i][j + 1] = silu_f(z.y + rb[j + 1]);
        }
    }
    __syncthreads();  // all GEMM1 reads done before overwrite

    // store h into sA k-major: sA[col][row]
#pragma unroll
    for (int jc = 0; jc < 8; ++jc) {
        const int col = (jc < 4) ? (tx * 4 + jc) : (64 + tx * 4 + (jc - 4));
        const float4 v = make_float4(h[0][jc], h[1][jc], h[2][jc], h[3][jc]);
        *(float4*)(sA + col * SA + ty * 4) = v;
    }
    __syncthreads();

    // ---- Layer 2 ----
    gemm128(sA, sW2, tx, ty, acc);
#pragma unroll
    for (int j = 0; j < 4; ++j) {
        rb[j]     = b2[tx * 4 + j];
        rb[4 + j] = b2[64 + tx * 4 + j];
    }
#pragma unroll
    for (int i = 0; i < 4; ++i) {
        const int row = rowBase + ty * 4 + i;
        const float2 z0 = unpack2(acc[i][0]);
        const float2 z1 = unpack2(acc[i][1]);
        const float2 z2 = unpack2(acc[i][2]);
        const float2 z3 = unpack2(acc[i][3]);
        const float4 va = make_float4(silu_f(z0.x + rb[0]), silu_f(z0.y + rb[1]),
                                      silu_f(z1.x + rb[2]), silu_f(z1.y + rb[3]));
        const float4 vb = make_float4(silu_f(z2.x + rb[4]), silu_f(z2.y + rb[5]),
                                      silu_f(z3.x + rb[6]), silu_f(z3.y + rb[7]));
        *(float4*)(out + (size_t)row * DIM + tx * 4)      = va;
        *(float4*)(out + (size_t)row * DIM + 64 + tx * 4) = vb;
    }
}

extern "C" void kernel_launch(void* const* d_in, const int* in_sizes, int n_in,
                              void* d_out, int out_size) {
    const float* t  = (const float*)d_in[0];
    const float* W1 = (const float*)d_in[1];
    const float* b1 = (const float*)d_in[2];
    const float* W2 = (const float*)d_in[3];
    const float* b2 = (const float*)d_in[4];
    float* out = (float*)d_out;

    const int B = in_sizes[0];
    const int smem_bytes = (2 * DIM * SW + DIM * SA) * (int)sizeof(float);  // ~198 KB

    cudaFuncSetAttribute(fused_timestep_mlp,
                         cudaFuncAttributeMaxDynamicSharedMemorySize, smem_bytes);

    fused_timestep_mlp<<<B / DIM, THREADS, smem_bytes>>>(t, W1, b1, W2, b2, out);
}

// round 4
// speedup vs baseline: 1.9488x; 1.9488x over previous
#include <cuda_runtime.h>
#include <cuda_bf16.h>
#include <cstdint>

#define DIM 128
#define NTH 256
#define PI_F 3.14159265358979323846f

// ---- smem byte offsets (each 128x128 bf16 tile = 32768 B, swizzled) ----
#define OFF_W1H 0
#define OFF_W1L 32768
#define OFF_W2H 65536
#define OFF_W2L 98304
#define OFF_AH  131072
#define OFF_AL  163840
#define OFF_B1  196608
#define OFF_B2  197120
#define SMEM_TOTAL 197632

// swizzled byte offset in a [128 rows x 128 k] bf16 tile, 256B/row.
// XOR of 16B-chunk index with (row&7) -> conflict-free ldmatrix & stores.
__device__ __forceinline__ uint32_t swz(int row, int kElem) {
    return (uint32_t)(row * 256) + (((uint32_t)(kElem * 2)) ^ (uint32_t)((row & 7) << 4));
}

__device__ __forceinline__ uint32_t smem_u32(const void* p) {
    uint32_t a;
    asm("{ .reg .u64 t; cvta.to.shared.u64 t, %1; cvt.u32.u64 %0, t; }" : "=r"(a) : "l"(p));
    return a;
}

__device__ __forceinline__ void ldsm4(uint32_t& r0, uint32_t& r1, uint32_t& r2, uint32_t& r3,
                                      uint32_t addr) {
    asm volatile("ldmatrix.sync.aligned.m8n8.x4.shared.b16 {%0,%1,%2,%3}, [%4];"
                 : "=r"(r0), "=r"(r1), "=r"(r2), "=r"(r3) : "r"(addr));
}

__device__ __forceinline__ void mma16816(float* c, const uint32_t* a, uint32_t b0, uint32_t b1) {
    asm volatile(
        "mma.sync.aligned.m16n8k16.row.col.f32.bf16.bf16.f32 "
        "{%0,%1,%2,%3}, {%4,%5,%6,%7}, {%8,%9}, {%0,%1,%2,%3};"
        : "+f"(c[0]), "+f"(c[1]), "+f"(c[2]), "+f"(c[3])
        : "r"(a[0]), "r"(a[1]), "r"(a[2]), "r"(a[3]), "r"(b0), "r"(b1));
}

__device__ __forceinline__ uint32_t pack2(__nv_bfloat16 a, __nv_bfloat16 b) {
    return ((uint32_t)__bfloat16_as_ushort(b) << 16) | (uint32_t)__bfloat16_as_ushort(a);
}

// split (x0,x1) at cols (k,k+1), k even, into hi/lo bf16 pairs; store swizzled
__device__ __forceinline__ void split_pair(char* sm, int baseHi, int baseLo,
                                           int row, int k, float x0, float x1) {
    const uint32_t off = swz(row, k);
    const __nv_bfloat16 h0 = __float2bfloat16(x0), h1 = __float2bfloat16(x1);
    const float r0 = x0 - __bfloat162float(h0), r1 = x1 - __bfloat162float(h1);
    *(uint32_t*)(sm + baseHi + off) = pack2(h0, h1);
    *(uint32_t*)(sm + baseLo + off) = pack2(__float2bfloat16(r0), __float2bfloat16(r1));
}

__device__ __forceinline__ float silu_f(float z) {
    return z / (1.0f + __expf(-z));
}

// One 128x128x128 GEMM, 3-pass bf16 split. Warp computes 32m x 64n.
// acc[mt][ntl][4], mt in {0,1} (16-row tiles), ntl in 0..7 (8-col tiles).
__device__ __forceinline__ void gemm_warp(uint32_t sb, int offAh, int offAl,
                                          int offWh, int offWl,
                                          int mg, int ng, int lane,
                                          float acc[2][8][4]) {
#pragma unroll
    for (int mt = 0; mt < 2; ++mt)
#pragma unroll
        for (int nt = 0; nt < 8; ++nt)
#pragma unroll
            for (int q = 0; q < 4; ++q) acc[mt][nt][q] = 0.0f;

    const int g = lane >> 3, i = lane & 7;
    // A-frag lane geometry: mats (m-low/k-low, m-high/k-low, m-low/k-high, m-high/k-high)
    const int aRowLoc = ((g & 1) << 3) + i;   // within 16-row tile
    const int aKoff   = (g >> 1) << 3;        // 0 or 8
    // W-frag lane geometry: mats (n-low/k-low, n-low/k-high, n-high/k-low, n-high/k-high)
    const int wRowLoc = ((g >> 1) << 3) + i;  // within 16-n pair
    const int wKoff   = (g & 1) << 3;

#pragma unroll
    for (int ks = 0; ks < 8; ++ks) {
        const int k0 = ks * 16;
        uint32_t ah[2][4], al[2][4];
#pragma unroll
        for (int mt = 0; mt < 2; ++mt) {
            const int row = mg * 32 + mt * 16 + aRowLoc;
            const int kk  = k0 + aKoff;
            ldsm4(ah[mt][0], ah[mt][1], ah[mt][2], ah[mt][3], sb + offAh + swz(row, kk));
            ldsm4(al[mt][0], al[mt][1], al[mt][2], al[mt][3], sb + offAl + swz(row, kk));
        }
#pragma unroll
        for (int np = 0; np < 4; ++np) {
            const int n0 = ng * 64 + np * 16;
            const int wrow = n0 + wRowLoc;
            const int wkk  = k0 + wKoff;
            uint32_t bh[4], bl[4];
            ldsm4(bh[0], bh[1], bh[2], bh[3], sb + offWh + swz(wrow, wkk));
            ldsm4(bl[0], bl[1], bl[2], bl[3], sb + offWl + swz(wrow, wkk));
#pragma unroll
            for (int q = 0; q < 2; ++q) {
                const int ntl = np * 2 + q;
#pragma unroll
                for (int mt = 0; mt < 2; ++mt) {
                    mma16816(acc[mt][ntl], ah[mt], bh[2 * q], bh[2 * q + 1]);  // hi*hi
                    mma16816(acc[mt][ntl], ah[mt], bl[2 * q], bl[2 * q + 1]);  // hi*lo
                    mma16816(acc[mt][ntl], al[mt], bh[2 * q], bh[2 * q + 1]);  // lo*hi
                }
            }
        }
    }
}

__global__ void __launch_bounds__(NTH, 1)
fused_timestep_mlp_mma(const float* __restrict__ t,
                       const float* __restrict__ W1,
                       const float* __restrict__ b1,
                       const float* __restrict__ W2,
                       const float* __restrict__ b2,
                       float* __restrict__ out,
                       int n_tiles) {
    extern __shared__ char sm[];
    const uint32_t sb = smem_u32(sm);
    const int tid = threadIdx.x;
    const int wid = tid >> 5;
    const int lane = tid & 31;
    const int mg = wid & 3;   // m-group: rows mg*32..+31
    const int ng = wid >> 2;  // n-half:  cols ng*64..+63

    // ---- load + split weights (once), biases ----
    {
        const int o  = tid >> 1;
        const int k0 = (tid & 1) * 64;
#pragma unroll
        for (int j = 0; j < 64; j += 4) {
            const float4 v1 = *(const float4*)(W1 + o * DIM + k0 + j);
            split_pair(sm, OFF_W1H, OFF_W1L, o, k0 + j,     v1.x, v1.y);
            split_pair(sm, OFF_W1H, OFF_W1L, o, k0 + j + 2, v1.z, v1.w);
            const float4 v2 = *(const float4*)(W2 + o * DIM + k0 + j);
            split_pair(sm, OFF_W2H, OFF_W2L, o, k0 + j,     v2.x, v2.y);
            split_pair(sm, OFF_W2H, OFF_W2L, o, k0 + j + 2, v2.z, v2.w);
        }
        if (tid < 128) ((float*)(sm + OFF_B1))[tid] = b1[tid];
        else           ((float*)(sm + OFF_B2))[tid - 128] = b2[tid - 128];
    }
    const float* sB1 = (const float*)(sm + OFF_B1);
    const float* sB2 = (const float*)(sm + OFF_B2);

    float acc[2][8][4];

    for (int tile = blockIdx.x; tile < n_tiles; tile += gridDim.x) {
        const int rowBase = tile * DIM;

        __syncthreads();  // prior GEMM2 smem reads done before A overwrite

        // ---- embedding -> A (split bf16 hi/lo) ----
        {
            const int row = tid >> 1;
            const int kh  = (tid & 1) * 64;
            const float tv = t[rowBase + row];
            const float p1 = tv * (PI_F / 128.0f);
            const float p2 = (1.0f - tv) * (PI_F / 128.0f);
#pragma unroll 4
            for (int j = 0; j < 64; j += 2) {
                const float d0 = (float)(kh + j), d1 = (float)(kh + j + 1);
                const float e0 = tv * __cosf(d0 * p1) + tv * __sinf(d0 * p2);
                const float e1 = tv * __cosf(d1 * p1) + tv * __sinf(d1 * p2);
                split_pair(sm, OFF_AH, OFF_AL, row, kh + j, e0, e1);
            }
        }
        __syncthreads();

        // ---- layer 1 GEMM ----
        gemm_warp(sb, OFF_AH, OFF_AL, OFF_W1H, OFF_W1L, mg, ng, lane, acc);
        __syncthreads();  // all GEMM1 reads done before epi writes A

        // ---- epilogue 1: silu -> A (split bf16) ----
#pragma unroll
        for (int mt = 0; mt < 2; ++mt) {
#pragma unroll
            for (int ntl = 0; ntl < 8; ++ntl) {
                const int n  = ng * 64 + ntl * 8 + 2 * (lane & 3);
                const int r0 = mg * 32 + mt * 16 + (lane >> 2);
                const float bb0 = sB1[n], bb1 = sB1[n + 1];
                const float* c = acc[mt][ntl];
                split_pair(sm, OFF_AH, OFF_AL, r0, n,
                           silu_f(c[0] + bb0), silu_f(c[1] + bb1));
                split_pair(sm, OFF_AH, OFF_AL, r0 + 8, n,
                           silu_f(c[2] + bb0), silu_f(c[3] + bb1));
            }
        }
        __syncthreads();

        // ---- layer 2 GEMM ----
        gemm_warp(sb, OFF_AH, OFF_AL, OFF_W2H, OFF_W2L, mg, ng, lane, acc);

        // ---- epilogue 2: silu -> gmem ----
#pragma unroll
        for (int mt = 0; mt < 2; ++mt) {
#pragma unroll
            for (int ntl = 0; ntl < 8; ++ntl) {
                const int n  = ng * 64 + ntl * 8 + 2 * (lane & 3);
                const int r0 = mg * 32 + mt * 16 + (lane >> 2);
                const float bb0 = sB2[n], bb1 = sB2[n + 1];
                const float* c = acc[mt][ntl];
                float2 v0 = make_float2(silu_f(c[0] + bb0), silu_f(c[1] + bb1));
                float2 v1 = make_float2(silu_f(c[2] + bb0), silu_f(c[3] + bb1));
                *(float2*)(out + (size_t)(rowBase + r0) * DIM + n)       = v0;
                *(float2*)(out + (size_t)(rowBase + r0 + 8) * DIM + n)   = v1;
            }
        }
    }
}

extern "C" void kernel_launch(void* const* d_in, const int* in_sizes, int n_in,
                              void* d_out, int out_size) {
    const float* t  = (const float*)d_in[0];
    const float* W1 = (const float*)d_in[1];
    const float* b1 = (const float*)d_in[2];
    const float* W2 = (const float*)d_in[3];
    const float* b2 = (const float*)d_in[4];
    float* out = (float*)d_out;

    const int B = in_sizes[0];
    const int n_tiles = B / DIM;

    int nsm = 148;
    cudaDeviceGetAttribute(&nsm, cudaDevAttrMultiProcessorCount, 0);
    const int grid = nsm < n_tiles ? nsm : n_tiles;

    cudaFuncSetAttribute(fused_timestep_mlp_mma,
                         cudaFuncAttributeMaxDynamicSharedMemorySize, SMEM_TOTAL);

    fused_timestep_mlp_mma<<<grid, NTH, SMEM_TOTAL>>>(t, W1, b1, W2, b2, out, n_tiles);
}

// round 5
// speedup vs baseline: 2.3789x; 1.2207x over previous
#include <cuda_runtime.h>
#include <cuda_bf16.h>
#include <cstdint>

#define DIM 128
#define NTH 512
#define PI_F 3.14159265358979323846f

// ---- smem byte offsets (each 128x128 bf16 tile = 32768 B, swizzled) ----
#define OFF_W1H 0
#define OFF_W1L 32768
#define OFF_W2H 65536
#define OFF_W2L 98304
#define OFF_AH  131072
#define OFF_AL  163840
#define OFF_B1  196608
#define OFF_B2  197120
#define SMEM_TOTAL 197632

// swizzled byte offset in a [128 rows x 128 k] bf16 tile, 256B/row.
__device__ __forceinline__ uint32_t swz(int row, int kElem) {
    return (uint32_t)(row * 256) + (((uint32_t)(kElem * 2)) ^ (uint32_t)((row & 7) << 4));
}

__device__ __forceinline__ uint32_t smem_u32(const void* p) {
    uint32_t a;
    asm("{ .reg .u64 t; cvta.to.shared.u64 t, %1; cvt.u32.u64 %0, t; }" : "=r"(a) : "l"(p));
    return a;
}

__device__ __forceinline__ void ldsm4(uint32_t& r0, uint32_t& r1, uint32_t& r2, uint32_t& r3,
                                      uint32_t addr) {
    asm volatile("ldmatrix.sync.aligned.m8n8.x4.shared.b16 {%0,%1,%2,%3}, [%4];"
                 : "=r"(r0), "=r"(r1), "=r"(r2), "=r"(r3) : "r"(addr));
}

__device__ __forceinline__ void mma16816(float* c, const uint32_t* a, uint32_t b0, uint32_t b1) {
    asm volatile(
        "mma.sync.aligned.m16n8k16.row.col.f32.bf16.bf16.f32 "
        "{%0,%1,%2,%3}, {%4,%5,%6,%7}, {%8,%9}, {%0,%1,%2,%3};"
        : "+f"(c[0]), "+f"(c[1]), "+f"(c[2]), "+f"(c[3])
        : "r"(a[0]), "r"(a[1]), "r"(a[2]), "r"(a[3]), "r"(b0), "r"(b1));
}

__device__ __forceinline__ uint32_t pack2(__nv_bfloat16 a, __nv_bfloat16 b) {
    return ((uint32_t)__bfloat16_as_ushort(b) << 16) | (uint32_t)__bfloat16_as_ushort(a);
}

// split (x0,x1) at cols (k,k+1), k even, into hi/lo bf16 pairs; store swizzled
__device__ __forceinline__ void split_pair(char* sm, int baseHi, int baseLo,
                                           int row, int k, float x0, float x1) {
    const uint32_t off = swz(row, k);
    const __nv_bfloat16 h0 = __float2bfloat16(x0), h1 = __float2bfloat16(x1);
    const float r0 = x0 - __bfloat162float(h0), r1 = x1 - __bfloat162float(h1);
    *(uint32_t*)(sm + baseHi + off) = pack2(h0, h1);
    *(uint32_t*)(sm + baseLo + off) = pack2(__float2bfloat16(r0), __float2bfloat16(r1));
}

__device__ __forceinline__ float silu_f(float z) {
    return z / (1.0f + __expf(-z));
}

// One 128x128x128 GEMM, 3-pass bf16 split. Warp computes 32m x 32n.
// acc[mt][ntl][4], mt in {0,1} (16-row tiles), ntl 0..3 (8-col tiles).
__device__ __forceinline__ void gemm_warp(uint32_t sb, int offAh, int offAl,
                                          int offWh, int offWl,
                                          int mg, int ng, int lane,
                                          float acc[2][4][4]) {
#pragma unroll
    for (int mt = 0; mt < 2; ++mt)
#pragma unroll
        for (int nt = 0; nt < 4; ++nt)
#pragma unroll
            for (int q = 0; q < 4; ++q) acc[mt][nt][q] = 0.0f;

    const int g = lane >> 3, i = lane & 7;
    const int aRowLoc = ((g & 1) << 3) + i;   // within 16-row tile
    const int aKoff   = (g >> 1) << 3;        // 0 or 8
    const int wRowLoc = ((g >> 1) << 3) + i;  // within 16-n pair
    const int wKoff   = (g & 1) << 3;

#pragma unroll
    for (int ks = 0; ks < 8; ++ks) {
        const int k0 = ks * 16;
        uint32_t ah[2][4], al[2][4];
#pragma unroll
        for (int mt = 0; mt < 2; ++mt) {
            const int row = mg * 32 + mt * 16 + aRowLoc;
            const int kk  = k0 + aKoff;
            ldsm4(ah[mt][0], ah[mt][1], ah[mt][2], ah[mt][3], sb + offAh + swz(row, kk));
            ldsm4(al[mt][0], al[mt][1], al[mt][2], al[mt][3], sb + offAl + swz(row, kk));
        }
#pragma unroll
        for (int np = 0; np < 2; ++np) {
            const int wrow = ng * 32 + np * 16 + wRowLoc;
            const int wkk  = k0 + wKoff;
            uint32_t bh[4], bl[4];
            ldsm4(bh[0], bh[1], bh[2], bh[3], sb + offWh + swz(wrow, wkk));
            ldsm4(bl[0], bl[1], bl[2], bl[3], sb + offWl + swz(wrow, wkk));
#pragma unroll
            for (int q = 0; q < 2; ++q) {
                const int ntl = np * 2 + q;
#pragma unroll
                for (int mt = 0; mt < 2; ++mt) {
                    mma16816(acc[mt][ntl], ah[mt], bh[2 * q], bh[2 * q + 1]);  // hi*hi
                    mma16816(acc[mt][ntl], ah[mt], bl[2 * q], bl[2 * q + 1]);  // hi*lo
                    mma16816(acc[mt][ntl], al[mt], bh[2 * q], bh[2 * q + 1]);  // lo*hi
                }
            }
        }
    }
}

__global__ void __launch_bounds__(NTH, 1)
fused_timestep_mlp_mma(const float* __restrict__ t,
                       const float* __restrict__ W1,
                       const float* __restrict__ b1,
                       const float* __restrict__ W2,
                       const float* __restrict__ b2,
                       float* __restrict__ out,
                       int n_tiles) {
    extern __shared__ char sm[];
    const uint32_t sb = smem_u32(sm);
    const int tid = threadIdx.x;
    const int wid = tid >> 5;
    const int lane = tid & 31;
    const int mg = wid & 3;   // m-group: rows mg*32..+31
    const int ng = wid >> 2;  // n-group: cols ng*32..+31

    // ---- load + split weights (once), biases ----
    {
        const int o  = tid >> 2;
        const int k0 = (tid & 3) * 32;
#pragma unroll
        for (int j = 0; j < 32; j += 4) {
            const float4 v1 = *(const float4*)(W1 + o * DIM + k0 + j);
            split_pair(sm, OFF_W1H, OFF_W1L, o, k0 + j,     v1.x, v1.y);
            split_pair(sm, OFF_W1H, OFF_W1L, o, k0 + j + 2, v1.z, v1.w);
            const float4 v2 = *(const float4*)(W2 + o * DIM + k0 + j);
            split_pair(sm, OFF_W2H, OFF_W2L, o, k0 + j,     v2.x, v2.y);
            split_pair(sm, OFF_W2H, OFF_W2L, o, k0 + j + 2, v2.z, v2.w);
        }
        if (tid < 128)                    ((float*)(sm + OFF_B1))[tid] = b1[tid];
        else if (tid < 256)               ((float*)(sm + OFF_B2))[tid - 128] = b2[tid - 128];
    }
    const float* sB1 = (const float*)(sm + OFF_B1);
    const float* sB2 = (const float*)(sm + OFF_B2);

    float acc[2][4][4];

    for (int tile = blockIdx.x; tile < n_tiles; tile += gridDim.x) {
        const int rowBase = tile * DIM;

        __syncthreads();  // prior GEMM2 smem reads done before A overwrite

        // ---- embedding -> A (split bf16 hi/lo) ----
        {
            const int row = tid >> 2;
            const int kh  = (tid & 3) * 32;
            const float tv = t[rowBase + row];
            const float p1 = tv * (PI_F / 128.0f);
            const float p2 = (1.0f - tv) * (PI_F / 128.0f);
#pragma unroll 4
            for (int j = 0; j < 32; j += 2) {
                const float d0 = (float)(kh + j), d1 = (float)(kh + j + 1);
                const float e0 = tv * __cosf(d0 * p1) + tv * __sinf(d0 * p2);
                const float e1 = tv * __cosf(d1 * p1) + tv * __sinf(d1 * p2);
                split_pair(sm, OFF_AH, OFF_AL, row, kh + j, e0, e1);
            }
        }
        __syncthreads();

        // ---- layer 1 GEMM ----
        gemm_warp(sb, OFF_AH, OFF_AL, OFF_W1H, OFF_W1L, mg, ng, lane, acc);
        __syncthreads();  // all GEMM1 reads done before epi writes A

        // ---- epilogue 1: silu -> A (split bf16) ----
#pragma unroll
        for (int mt = 0; mt < 2; ++mt) {
#pragma unroll
            for (int ntl = 0; ntl < 4; ++ntl) {
                const int n  = ng * 32 + ntl * 8 + 2 * (lane & 3);
                const int r0 = mg * 32 + mt * 16 + (lane >> 2);
                const float bb0 = sB1[n], bb1 = sB1[n + 1];
                const float* c = acc[mt][ntl];
                split_pair(sm, OFF_AH, OFF_AL, r0, n,
                           silu_f(c[0] + bb0), silu_f(c[1] + bb1));
                split_pair(sm, OFF_AH, OFF_AL, r0 + 8, n,
                           silu_f(c[2] + bb0), silu_f(c[3] + bb1));
            }
        }
        __syncthreads();

        // ---- layer 2 GEMM ----
        gemm_warp(sb, OFF_AH, OFF_AL, OFF_W2H, OFF_W2L, mg, ng, lane, acc);

        // ---- epilogue 2: silu -> gmem ----
#pragma unroll
        for (int mt = 0; mt < 2; ++mt) {
#pragma unroll
            for (int ntl = 0; ntl < 4; ++ntl) {
                const int n  = ng * 32 + ntl * 8 + 2 * (lane & 3);
                const int r0 = mg * 32 + mt * 16 + (lane >> 2);
                const float bb0 = sB2[n], bb1 = sB2[n + 1];
                const float* c = acc[mt][ntl];
                float2 v0 = make_float2(silu_f(c[0] + bb0), silu_f(c[1] + bb1));
                float2 v1 = make_float2(silu_f(c[2] + bb0), silu_f(c[3] + bb1));
                *(float2*)(out + (size_t)(rowBase + r0) * DIM + n)     = v0;
                *(float2*)(out + (size_t)(rowBase + r0 + 8) * DIM + n) = v1;
            }
        }
    }
}

extern "C" void kernel_launch(void* const* d_in, const int* in_sizes, int n_in,
                              void* d_out, int out_size) {
    const float* t  = (const float*)d_in[0];
    const float* W1 = (const float*)d_in[1];
    const float* b1 = (const float*)d_in[2];
    const float* W2 = (const float*)d_in[3];
    const float* b2 = (const float*)d_in[4];
    float* out = (float*)d_out;

    const int B = in_sizes[0];
    const int n_tiles = B / DIM;

    int nsm = 148;
    cudaDeviceGetAttribute(&nsm, cudaDevAttrMultiProcessorCount, 0);
    const int grid = nsm < n_tiles ? nsm : n_tiles;

    cudaFuncSetAttribute(fused_timestep_mlp_mma,
                         cudaFuncAttributeMaxDynamicSharedMemorySize, SMEM_TOTAL);

    fused_timestep_mlp_mma<<<grid, NTH, SMEM_TOTAL>>>(t, W1, b1, W2, b2, out, n_tiles);
}